// round 3
// baseline (speedup 1.0000x reference)
#include <cuda_runtime.h>
#include <math.h>

#define PS      32
#define NPIX    1024          // 32*32
#define NBINS   36
#define THREADS 128
#define HSTRIDE 37            // 36 bins + 1 pad; 37 mod 32 = 5 (coprime) -> per-row bank permutation

__global__ __launch_bounds__(THREADS, 8)
void orientation_kernel(const float* __restrict__ x,
                        const float* __restrict__ gxw,
                        const float* __restrict__ gyw,
                        const float* __restrict__ smw,
                        const float* __restrict__ gk,
                        float* __restrict__ out)
{
    __shared__ float xs[NPIX];                  // patch
    __shared__ float gks[NPIX];                 // gaussian window (same for all blocks)
    __shared__ float hist[THREADS * HSTRIDE];   // per-thread private histograms
    __shared__ float hred[NBINS];               // reduced histogram

    const int   tid = threadIdx.x;
    const int   blk = blockIdx.x;
    const float TWO_PI_F = 6.283185307179586f;
    const float PI_F     = 3.141592653589793f;

    // ---- zero private histogram rows ----
    #pragma unroll
    for (int i = 0; i < HSTRIDE; i++)
        hist[tid * HSTRIDE + i] = 0.0f;

    // ---- stage patch + gaussian window to smem (coalesced float4) ----
    {
        const float4* xin = (const float4*)(x + (size_t)blk * NPIX);
        const float4* gin = (const float4*)gk;
        float4* xs4 = (float4*)xs;
        float4* gk4 = (float4*)gks;
        #pragma unroll
        for (int i = 0; i < NPIX / 4 / THREADS; i++) {
            xs4[tid + i * THREADS] = xin[tid + i * THREADS];
            gk4[tid + i * THREADS] = gin[tid + i * THREADS];
        }
    }
    const float gw0 = gxw[0], gw1 = gxw[1], gw2 = gxw[2];
    const float hw0 = gyw[0], hw1 = gyw[1], hw2 = gyw[2];
    __syncthreads();

    // ---- main loop: 8 pixels per thread; each warp covers full 32-wide rows ----
    #pragma unroll
    for (int i = 0; i < NPIX / THREADS; i++) {
        const int p = tid + i * THREADS;
        const int r = p >> 5;
        const int c = p & 31;

        const float xc = xs[p];
        const float xl = xs[r * PS + (c > 0      ? c - 1 : 0)];
        const float xr = xs[r * PS + (c < PS - 1 ? c + 1 : PS - 1)];
        const float xu = xs[(r > 0      ? r - 1 : 0)      * PS + c];
        const float xd = xs[(r < PS - 1 ? r + 1 : PS - 1) * PS + c];

        const float gxv = gw0 * xl + gw1 * xc + gw2 * xr;
        const float gyv = hw0 * xu + hw1 * xc + hw2 * xd;
        const float mag = sqrtf(gxv * gxv + gyv * gyv + 1e-10f) * gks[p];

        if (mag > 0.001f) {
            // Mirror the reference op-for-op (fp32): ori -> mod 2pi -> *36/2pi
            const float ori = atan2f(gyv, gxv);
            const float m   = ori - floorf(ori / TWO_PI_F) * TWO_PI_F;   // jnp.mod
            const float ob  = ((float)NBINS * m) / TWO_PI_F;
            const float bf  = floorf(ob);
            const float w   = (1.0f - (ob - bf)) * mag;                  // wo0
            int bin = ((int)bf) % NBINS;                                 // handles ob==36 edge
            hist[tid * HSTRIDE + bin] += w;
        }
    }
    __syncthreads();

    // ---- reduce 128 private rows -> 36 bins ----
    if (tid < NBINS) {
        float s0 = 0.f, s1 = 0.f, s2 = 0.f, s3 = 0.f;
        #pragma unroll
        for (int r = 0; r < THREADS; r += 4) {
            s0 += hist[(r + 0) * HSTRIDE + tid];
            s1 += hist[(r + 1) * HSTRIDE + tid];
            s2 += hist[(r + 2) * HSTRIDE + tid];
            s3 += hist[(r + 3) * HSTRIDE + tid];
        }
        hred[tid] = ((s0 + s1) + (s2 + s3)) * (1.0f / (float)NPIX);
    }
    __syncthreads();

    // ---- angular smoothing (zero pad) + first-occurrence argmax + angle ----
    if (tid == 0) {
        const float w0 = smw[0], w1 = smw[1], w2 = smw[2];
        float best = -INFINITY;
        int   bi   = 0;
        #pragma unroll
        for (int k = 0; k < NBINS; k++) {
            const float l  = (k > 0)         ? hred[k - 1] : 0.0f;
            const float rr = (k < NBINS - 1) ? hred[k + 1] : 0.0f;
            const float sm = w0 * l + w1 * hred[k] + w2 * rr;
            if (sm > best) { best = sm; bi = k; }
        }
        out[blk] = -((TWO_PI_F * (float)bi) / (float)NBINS - PI_F);
    }
}

extern "C" void kernel_launch(void* const* d_in, const int* in_sizes, int n_in,
                              void* d_out, int out_size)
{
    const float* x   = (const float*)d_in[0];   // [B,1,32,32]
    const float* gxw = (const float*)d_in[1];   // [3]
    const float* gyw = (const float*)d_in[2];   // [3]
    const float* smw = (const float*)d_in[3];   // [3]
    const float* gk  = (const float*)d_in[4];   // [32,32]
    float* out = (float*)d_out;                 // [B]

    const int B = in_sizes[0] / NPIX;
    orientation_kernel<<<B, THREADS>>>(x, gxw, gyw, smw, gk, out);
}

// round 4
// speedup vs baseline: 1.2362x; 1.2362x over previous
#include <cuda_runtime.h>
#include <math.h>

#define PS      32
#define NPIX    1024
#define NBINS   36
#define THREADS 128
#define HSTRIDE 37   // 36 bins + pad; 37 mod 32 = 5 (coprime) -> bank permutation per row

__global__ __launch_bounds__(THREADS, 8)
void orientation_kernel(const float* __restrict__ x,
                        const float* __restrict__ gxw,
                        const float* __restrict__ gyw,
                        const float* __restrict__ smw,
                        const float* __restrict__ gk,
                        float* __restrict__ out)
{
    __shared__ float hist[THREADS * HSTRIDE];   // per-thread private histograms
    __shared__ float hred[NBINS];

    const int tid  = threadIdx.x;
    const int lane = tid & 31;      // column
    const int wrp  = tid >> 5;      // warp -> 8-row band
    const int blk  = blockIdx.x;
    const float TWO_PI_F = 6.283185307179586f;
    const float PI_F     = 3.141592653589793f;

    // ---- zero private histogram row (own row only -> no sync needed) ----
    #pragma unroll
    for (int i = 0; i < HSTRIDE; i++)
        hist[tid * HSTRIDE + i] = 0.0f;

    const float gw0 = gxw[0], gw1 = gxw[1], gw2 = gxw[2];
    const float hw0 = gyw[0], hw1 = gyw[1], hw2 = gyw[2];

    // ---- preload 10-row column window (replicate-clamped) + gaussian, coalesced ----
    const float* xc = x + (size_t)blk * NPIX + lane;
    const int r0 = wrp * 8;

    float v[10];
    #pragma unroll
    for (int i = 0; i < 10; i++) {
        int r = r0 + i - 1;
        r = r < 0 ? 0 : (r > PS - 1 ? PS - 1 : r);
        v[i] = xc[r * PS];
    }
    float g[8];
    #pragma unroll
    for (int i = 0; i < 8; i++)
        g[i] = gk[(r0 + i) * PS + lane];   // 4KB, L1-resident across blocks

    float* hrow = hist + tid * HSTRIDE;

    // ---- 8 pixels per thread: vertical = register chain, horizontal = shfl ----
    #pragma unroll
    for (int i = 0; i < 8; i++) {
        const float cc = v[i + 1];
        const float xl = __shfl_up_sync(0xffffffffu, cc, 1);    // lane 0 -> own (edge pad)
        const float xr = __shfl_down_sync(0xffffffffu, cc, 1);  // lane 31 -> own (edge pad)

        const float gxv = gw0 * xl   + gw1 * cc + gw2 * xr;
        const float gyv = hw0 * v[i] + hw1 * cc + hw2 * v[i + 2];
        const float mag = sqrtf(gxv * gxv + gyv * gyv + 1e-10f) * g[i];

        if (mag > 0.001f) {
            const float ori = atan2f(gyv, gxv);
            // jnp.mod(ori, 2pi): floor(ori/2pi) in {-1,0} -> bitwise-equal select
            const float m   = (ori < 0.0f) ? ori + TWO_PI_F : ori;
            const float ob  = (36.0f * m) / TWO_PI_F;          // keep div.rn (bit-match)
            const float bf  = floorf(ob);
            const float w   = (1.0f - (ob - bf)) * mag;        // wo0
            int bin = (int)bf;
            if (bin >= NBINS) bin = 0;                          // ob==36 edge -> mod
            hrow[bin] += w;
        }
    }
    __syncthreads();

    // ---- reduce 128 private rows -> 36 bins ----
    if (tid < NBINS) {
        float s0 = 0.f, s1 = 0.f, s2 = 0.f, s3 = 0.f;
        #pragma unroll
        for (int r = 0; r < THREADS; r += 4) {
            s0 += hist[(r + 0) * HSTRIDE + tid];
            s1 += hist[(r + 1) * HSTRIDE + tid];
            s2 += hist[(r + 2) * HSTRIDE + tid];
            s3 += hist[(r + 3) * HSTRIDE + tid];
        }
        hred[tid] = ((s0 + s1) + (s2 + s3)) * (1.0f / (float)NPIX);
    }
    __syncthreads();

    // ---- angular smoothing (zero pad) + first-occurrence argmax -> angle ----
    if (tid == 0) {
        const float w0 = smw[0], w1 = smw[1], w2 = smw[2];
        float best = -INFINITY;
        int   bi   = 0;
        #pragma unroll
        for (int k = 0; k < NBINS; k++) {
            const float l  = (k > 0)         ? hred[k - 1] : 0.0f;
            const float rr = (k < NBINS - 1) ? hred[k + 1] : 0.0f;
            const float sm = w0 * l + w1 * hred[k] + w2 * rr;
            if (sm > best) { best = sm; bi = k; }
        }
        out[blk] = -((TWO_PI_F * (float)bi) / (float)NBINS - PI_F);
    }
}

extern "C" void kernel_launch(void* const* d_in, const int* in_sizes, int n_in,
                              void* d_out, int out_size)
{
    const float* x   = (const float*)d_in[0];   // [B,1,32,32]
    const float* gxw = (const float*)d_in[1];   // [3]
    const float* gyw = (const float*)d_in[2];   // [3]
    const float* smw = (const float*)d_in[3];   // [3]
    const float* gk  = (const float*)d_in[4];   // [32,32]
    float* out = (float*)d_out;                 // [B]

    const int B = in_sizes[0] / NPIX;
    orientation_kernel<<<B, THREADS>>>(x, gxw, gyw, smw, gk, out);
}

// round 5
// speedup vs baseline: 1.3760x; 1.1131x over previous
#include <cuda_runtime.h>
#include <math.h>

#define PS      32
#define NPIX    1024
#define NBINS   36
#define THREADS 128
#define HSTRIDE 37   // 36 bins + pad; 37 mod 32 = 5 (coprime) -> bank permutation per row

__device__ __forceinline__ float sqrt_approx(float v) {
    float r;
    asm("sqrt.approx.f32 %0, %1;" : "=f"(r) : "f"(v));
    return r;
}

__global__ __launch_bounds__(THREADS, 8)
void orientation_kernel(const float* __restrict__ x,
                        const float* __restrict__ gxw,
                        const float* __restrict__ gyw,
                        const float* __restrict__ smw,
                        const float* __restrict__ gk,
                        float* __restrict__ out)
{
    __shared__ float hist[THREADS * HSTRIDE];   // per-thread private histograms
    __shared__ float hred[NBINS];

    const int tid  = threadIdx.x;
    const int lane = tid & 31;
    const int wrp  = tid >> 5;
    const int q    = lane & 7;          // col-quad: cols 4q..4q+3
    const int rg   = lane >> 3;         // rowgroup within warp
    const int blk  = blockIdx.x;

    const float TWO_PI_F = __int_as_float(0x40C90FDB);   // RN(2*pi)
    const float INV_2PI  = __int_as_float(0x3E22F983);   // RN(1/(2*pi))
    const float PI_F     = 3.141592653589793f;

    // ---- zero histogram block-cooperatively with STS.128 ----
    {
        float4 z = make_float4(0.f, 0.f, 0.f, 0.f);
        float4* h4 = (float4*)hist;
        #pragma unroll
        for (int i = 0; i < (THREADS * HSTRIDE + 3) / 4; i += THREADS) {
            int idx = i + tid;
            if (idx < (THREADS * HSTRIDE) / 4) h4[idx] = z;
        }
    }

    const float gw0 = gxw[0], gw1 = gxw[1], gw2 = gxw[2];
    const float hw0 = gyw[0], hw1 = gyw[1], hw2 = gyw[2];

    // ---- vectorized loads: thread owns rows rb,rb+1 x cols 4q..4q+3 ----
    const int g  = wrp * 4 + rg;        // global rowgroup 0..15
    const int rb = 2 * g;               // base row (even)
    const int rm = (rb - 1 < 0) ? 0 : rb - 1;
    const int rp = (rb + 2 > PS - 1) ? PS - 1 : rb + 2;

    const float4* xp = (const float4*)(x + (size_t)blk * NPIX);
    const float4* gp = (const float4*)gk;

    const float4 v0 = xp[rm * 8 + q];          // row rb-1 (clamped)
    const float4 v1 = xp[rb * 8 + q];          // row rb
    const float4 v2 = xp[(rb + 1) * 8 + q];    // row rb+1
    const float4 v3 = xp[rp * 8 + q];          // row rb+2 (clamped)
    const float4 g0 = gp[rb * 8 + q];
    const float4 g1 = gp[(rb + 1) * 8 + q];

    float* hrow = hist + tid * HSTRIDE;
    __syncthreads();   // hist zeroed by all threads

    // ---- process 2 rows x 4 cols ----
    #pragma unroll
    for (int i = 0; i < 2; i++) {
        const float4 up = (i == 0) ? v0 : v1;
        const float4 ce = (i == 0) ? v1 : v2;
        const float4 dn = (i == 0) ? v2 : v3;
        const float4 gg = (i == 0) ? g0 : g1;

        // horizontal neighbors across quad edges (replicate-pad at patch edges)
        float lt = __shfl_up_sync(0xffffffffu, ce.w, 1);
        float rt = __shfl_down_sync(0xffffffffu, ce.x, 1);
        if (q == 0) lt = ce.x;
        if (q == 7) rt = ce.w;

        const float cl[4] = { lt,   ce.x, ce.y, ce.z };
        const float cc[4] = { ce.x, ce.y, ce.z, ce.w };
        const float cr[4] = { ce.y, ce.z, ce.w, rt   };
        const float cu[4] = { up.x, up.y, up.z, up.w };
        const float cd[4] = { dn.x, dn.y, dn.z, dn.w };
        const float cg[4] = { gg.x, gg.y, gg.z, gg.w };

        #pragma unroll
        for (int j = 0; j < 4; j++) {
            const float gxv = gw0 * cl[j] + gw1 * cc[j] + gw2 * cr[j];
            const float gyv = hw0 * cu[j] + hw1 * cc[j] + hw2 * cd[j];
            const float mag = sqrt_approx(gxv * gxv + gyv * gyv + 1e-10f) * cg[j];

            if (mag > 0.001f) {
                const float ori = atan2f(gyv, gxv);
                // jnp.mod(ori, 2pi): floor in {-1,0} -> bitwise-equal select
                const float m    = (ori < 0.0f) ? ori + TWO_PI_F : ori;
                const float xnum = 36.0f * m;
                // Markstein constant division: ob = xnum / 2pi, correctly rounded
                const float qd = xnum * INV_2PI;
                const float rr = fmaf(-TWO_PI_F, qd, xnum);
                const float ob = fmaf(rr, INV_2PI, qd);

                const float bf = floorf(ob);
                const float w  = (1.0f - (ob - bf)) * mag;     // wo0
                int bin = (int)bf;
                if (bin >= NBINS) bin = 0;                     // ob==36 edge -> mod
                hrow[bin] += w;
            }
        }
    }
    __syncthreads();

    // ---- reduce 128 private rows -> 36 bins ----
    if (tid < NBINS) {
        float s0 = 0.f, s1 = 0.f, s2 = 0.f, s3 = 0.f;
        #pragma unroll
        for (int r = 0; r < THREADS; r += 4) {
            s0 += hist[(r + 0) * HSTRIDE + tid];
            s1 += hist[(r + 1) * HSTRIDE + tid];
            s2 += hist[(r + 2) * HSTRIDE + tid];
            s3 += hist[(r + 3) * HSTRIDE + tid];
        }
        hred[tid] = ((s0 + s1) + (s2 + s3)) * (1.0f / (float)NPIX);
    }
    __syncthreads();

    // ---- angular smoothing (zero pad) + first-occurrence argmax -> angle ----
    if (tid == 0) {
        const float w0 = smw[0], w1 = smw[1], w2 = smw[2];
        float best = -INFINITY;
        int   bi   = 0;
        #pragma unroll
        for (int k = 0; k < NBINS; k++) {
            const float l  = (k > 0)         ? hred[k - 1] : 0.0f;
            const float r  = (k < NBINS - 1) ? hred[k + 1] : 0.0f;
            const float sm = w0 * l + w1 * hred[k] + w2 * r;
            if (sm > best) { best = sm; bi = k; }
        }
        out[blk] = -((TWO_PI_F * (float)bi) / (float)NBINS - PI_F);
    }
}

extern "C" void kernel_launch(void* const* d_in, const int* in_sizes, int n_in,
                              void* d_out, int out_size)
{
    const float* x   = (const float*)d_in[0];   // [B,1,32,32]
    const float* gxw = (const float*)d_in[1];   // [3]
    const float* gyw = (const float*)d_in[2];   // [3]
    const float* smw = (const float*)d_in[3];   // [3]
    const float* gk  = (const float*)d_in[4];   // [32,32]
    float* out = (float*)d_out;                 // [B]

    const int B = in_sizes[0] / NPIX;
    orientation_kernel<<<B, THREADS>>>(x, gxw, gyw, smw, gk, out);
}